// round 3
// baseline (speedup 1.0000x reference)
#include <cuda_runtime.h>
#include <math.h>

// Problem constants
#define Bc   8
#define Hh   8
#define NT   1024    // N*T query rows per batch
#define NKT  2048    // (N+NC)*T key rows per batch
#define Cdim 512
#define Dh   64

// ---------------- scratch (device globals; no allocation allowed) ----------
__device__ float g_q[(size_t)Bc * Hh * NT  * Dh];   // [B,H,NT,Dh]
__device__ float g_k[(size_t)Bc * Hh * NKT * Dh];   // [B,H,NKT,Dh]
__device__ float g_v[(size_t)Bc * Hh * NKT * Dh];   // [B,H,NKT,Dh]
__device__ float g_y[(size_t)Bc * NT * Cdim];       // [B,NT,C] attention output
__device__ int   g_maskmode;                        // 0=uint8, 1=int32, 2=float32

// ---------------- mask dtype detection -------------------------------------
// Serialized bool masks may arrive as uint8 (1B), int32, or float32. Detect by
// byte pattern over the first 8KB:
//  - float32 1.0f has byte3 == 0x3f        -> mode 2
//  - else any nonzero byte at idx%4 != 0   -> mode 0 (uint8 random 0/1)
//  - else                                  -> mode 1 (int32 0/1, little-endian)
__global__ void detect_mask_mode(const unsigned char* __restrict__ m) {
    bool hi = false, f3 = false;
    for (int i = threadIdx.x; i < 8192; i += blockDim.x) {
        unsigned char v = m[i];
        int p = i & 3;
        if (p == 3 && v == 0x3f) f3 = true;
        if (p != 0 && v != 0)    hi = true;
    }
    int a3 = __syncthreads_or(f3 ? 1 : 0);
    int ah = __syncthreads_or(hi ? 1 : 0);
    if (threadIdx.x == 0)
        g_maskmode = a3 ? 2 : (ah ? 0 : 1);
}

__device__ __forceinline__ int mask_at(const void* mp, size_t idx, int mode) {
    if (mode == 0) return ((const unsigned char*)mp)[idx] != 0;
    if (mode == 1) return ((const int*)mp)[idx] != 0;
    return ((const float*)mp)[idx] != 0.0f;
}

// ---------------- GEMM: Y = A @ W^T ----------------------------------------
// A rows gathered from x (modeIn=0) or concat(x,c) (modeIn=1).
// Output: modeOut=0 -> head-split [B,H,Mrows,Dh]; modeOut=1 -> flat [rows, C].
#define GBM 128
#define GBN 128
#define GBK 16
#define GPAD 132   // padded row stride (floats) -> <=2-way STS conflicts, 16B aligned

__global__ __launch_bounds__(256) void gemm_kernel(
    const float* __restrict__ A0, const float* __restrict__ A1,
    const float* __restrict__ W, float* __restrict__ outp,
    int MrowsPerB, int modeIn, int modeOut)
{
    __shared__ float As[GBK][GPAD];
    __shared__ float Bs[GBK][GPAD];

    const int tid = threadIdx.x;
    const int m0  = blockIdx.y * GBM;
    const int n0  = blockIdx.x * GBN;
    const int lr  = tid >> 2;          // 0..63
    const int lc  = (tid & 3) << 2;    // 0,4,8,12

    const float* arow[2];
    const float* brow[2];
#pragma unroll
    for (int p = 0; p < 2; p++) {
        int gm = m0 + lr + p * 64;
        int b  = gm / MrowsPerB;
        int m  = gm - b * MrowsPerB;
        if (modeIn == 0 || m < NT)
            arow[p] = A0 + ((size_t)b * NT + m) * Cdim;
        else
            arow[p] = A1 + ((size_t)b * NT + (m - NT)) * Cdim;
        brow[p] = W + (size_t)(n0 + lr + p * 64) * Cdim;
    }

    float acc[8][8];
#pragma unroll
    for (int i = 0; i < 8; i++)
#pragma unroll
        for (int j = 0; j < 8; j++) acc[i][j] = 0.f;

    const int ty = tid >> 4;     // 0..15
    const int tx = tid & 15;     // 0..15

    for (int k0 = 0; k0 < Cdim; k0 += GBK) {
#pragma unroll
        for (int p = 0; p < 2; p++) {
            float4 a  = *(const float4*)(arow[p] + k0 + lc);
            As[lc + 0][lr + p * 64] = a.x;
            As[lc + 1][lr + p * 64] = a.y;
            As[lc + 2][lr + p * 64] = a.z;
            As[lc + 3][lr + p * 64] = a.w;
            float4 bv = *(const float4*)(brow[p] + k0 + lc);
            Bs[lc + 0][lr + p * 64] = bv.x;
            Bs[lc + 1][lr + p * 64] = bv.y;
            Bs[lc + 2][lr + p * 64] = bv.z;
            Bs[lc + 3][lr + p * 64] = bv.w;
        }
        __syncthreads();
#pragma unroll
        for (int kk = 0; kk < GBK; kk++) {
            float4 ta0 = *(const float4*)&As[kk][ty * 8];
            float4 ta1 = *(const float4*)&As[kk][ty * 8 + 4];
            float4 tb0 = *(const float4*)&Bs[kk][tx * 8];
            float4 tb1 = *(const float4*)&Bs[kk][tx * 8 + 4];
            float a[8]  = {ta0.x, ta0.y, ta0.z, ta0.w, ta1.x, ta1.y, ta1.z, ta1.w};
            float bb[8] = {tb0.x, tb0.y, tb0.z, tb0.w, tb1.x, tb1.y, tb1.z, tb1.w};
#pragma unroll
            for (int i = 0; i < 8; i++)
#pragma unroll
                for (int j = 0; j < 8; j++)
                    acc[i][j] = fmaf(a[i], bb[j], acc[i][j]);
        }
        __syncthreads();
    }

    const int gn0 = n0 + tx * 8;
#pragma unroll
    for (int i = 0; i < 8; i++) {
        int gm = m0 + ty * 8 + i;
        float* op;
        if (modeOut == 0) {
            int b  = gm / MrowsPerB;
            int m  = gm - b * MrowsPerB;
            int h  = gn0 >> 6;
            int d0 = gn0 & 63;
            op = outp + (((size_t)(b * Hh + h)) * MrowsPerB + m) * Dh + d0;
        } else {
            op = outp + (size_t)gm * Cdim + gn0;
        }
        *(float4*)op       = make_float4(acc[i][0], acc[i][1], acc[i][2], acc[i][3]);
        *(float4*)(op + 4) = make_float4(acc[i][4], acc[i][5], acc[i][6], acc[i][7]);
    }
}

// ---------------- Flash attention ------------------------------------------
// grid (NT/64, H, B), 256 threads. 64 query rows per block, Dh=64.
// Online softmax; masked scores = -1e30 (NaN-free recurrence).
#define TPAD 68
#define ATT_SMEM_FLOATS (4 * 64 * TPAD + 128)
#define ATT_SMEM_BYTES  (ATT_SMEM_FLOATS * 4)

__global__ __launch_bounds__(256) void attn_kernel(
    const float* __restrict__ qg, const float* __restrict__ kg,
    const float* __restrict__ vg, const void* __restrict__ maskp,
    float* __restrict__ yg)
{
    extern __shared__ float sm[];
    float* Qs   = sm;                 // [64][TPAD]
    float* Ks   = Qs + 64 * TPAD;
    float* Vs   = Ks + 64 * TPAD;
    float* Ps   = Vs + 64 * TPAD;
    float* mrow = Ps + 64 * TPAD;     // [64]
    float* lrow = mrow + 64;          // [64]

    const int tid = threadIdx.x;
    const int b = blockIdx.z, h = blockIdx.y, qt = blockIdx.x;
    const int ty = tid >> 4, tx = tid & 15;
    const int rq = ty * 4, ck = tx * 4;
    const int mode = g_maskmode;

    // load Q tile (coalesced float4)
    const float* qbase = qg + (((size_t)(b * Hh + h)) * NT + qt * 64) * Dh;
#pragma unroll
    for (int i = 0; i < 4; i++) {
        int e = tid + i * 256;
        int r = e >> 4, c4 = (e & 15) << 2;
        *(float4*)&Qs[r * TPAD + c4] = *(const float4*)(qbase + r * Dh + c4);
    }
    if (tid < 64) { mrow[tid] = -1e30f; lrow[tid] = 0.f; }

    float acc[4][4];
#pragma unroll
    for (int i = 0; i < 4; i++)
#pragma unroll
        for (int j = 0; j < 4; j++) acc[i][j] = 0.f;

    const float* kbase = kg + ((size_t)(b * Hh + h)) * NKT * Dh;
    const float* vbase = vg + ((size_t)(b * Hh + h)) * NKT * Dh;
    const size_t mbase0 = ((size_t)b * NT + (size_t)qt * 64) * NKT;

    for (int kt = 0; kt < NKT / 64; kt++) {
        __syncthreads();   // previous iteration done with Ks/Vs/Ps
#pragma unroll
        for (int i = 0; i < 4; i++) {
            int e = tid + i * 256;
            int r = e >> 4, c4 = (e & 15) << 2;
            *(float4*)&Ks[r * TPAD + c4] = *(const float4*)(kbase + (size_t)(kt * 64 + r) * Dh + c4);
            *(float4*)&Vs[r * TPAD + c4] = *(const float4*)(vbase + (size_t)(kt * 64 + r) * Dh + c4);
        }
        __syncthreads();

        // S = Q K^T tile (4x4 per thread, vectorized over d)
        float s[4][4];
#pragma unroll
        for (int i = 0; i < 4; i++)
#pragma unroll
            for (int j = 0; j < 4; j++) s[i][j] = 0.f;

#pragma unroll
        for (int d4 = 0; d4 < Dh; d4 += 4) {
            float4 qv[4], kv[4];
#pragma unroll
            for (int i = 0; i < 4; i++) qv[i] = *(const float4*)&Qs[(rq + i) * TPAD + d4];
#pragma unroll
            for (int j = 0; j < 4; j++) kv[j] = *(const float4*)&Ks[(ck + j) * TPAD + d4];
#pragma unroll
            for (int i = 0; i < 4; i++)
#pragma unroll
                for (int j = 0; j < 4; j++)
                    s[i][j] += qv[i].x * kv[j].x + qv[i].y * kv[j].y +
                               qv[i].z * kv[j].z + qv[i].w * kv[j].w;
        }

        // mask + scale + online softmax update
#pragma unroll
        for (int i = 0; i < 4; i++) {
            size_t moff = mbase0 + (size_t)(rq + i) * NKT + (size_t)kt * 64 + ck;
            float sv[4];
#pragma unroll
            for (int j = 0; j < 4; j++)
                sv[j] = mask_at(maskp, moff + j, mode) ? -1e30f : s[i][j] * 0.125f;

            float rm = fmaxf(fmaxf(sv[0], sv[1]), fmaxf(sv[2], sv[3]));
            rm = fmaxf(rm, __shfl_xor_sync(0xffffffffu, rm, 1));
            rm = fmaxf(rm, __shfl_xor_sync(0xffffffffu, rm, 2));
            rm = fmaxf(rm, __shfl_xor_sync(0xffffffffu, rm, 4));
            rm = fmaxf(rm, __shfl_xor_sync(0xffffffffu, rm, 8));

            float mold = mrow[rq + i];
            float mnew = fmaxf(mold, rm);
            float corr = __expf(mold - mnew);

            float p0 = __expf(sv[0] - mnew);
            float p1 = __expf(sv[1] - mnew);
            float p2 = __expf(sv[2] - mnew);
            float p3 = __expf(sv[3] - mnew);
            *(float4*)&Ps[(rq + i) * TPAD + ck] = make_float4(p0, p1, p2, p3);
            float rs = p0 + p1 + p2 + p3;
            rs += __shfl_xor_sync(0xffffffffu, rs, 1);
            rs += __shfl_xor_sync(0xffffffffu, rs, 2);
            rs += __shfl_xor_sync(0xffffffffu, rs, 4);
            rs += __shfl_xor_sync(0xffffffffu, rs, 8);

#pragma unroll
            for (int j = 0; j < 4; j++) acc[i][j] *= corr;
            if (tx == 0) {
                mrow[rq + i] = mnew;
                lrow[rq + i] = lrow[rq + i] * corr + rs;
            }
        }
        __syncthreads();   // Ps complete, mrow/lrow updated

        // acc += P V (vectorized over kc)
#pragma unroll
        for (int kc0 = 0; kc0 < 64; kc0 += 4) {
            float4 vv[4];
#pragma unroll
            for (int u = 0; u < 4; u++) vv[u] = *(const float4*)&Vs[(kc0 + u) * TPAD + ck];
#pragma unroll
            for (int i = 0; i < 4; i++) {
                float4 pv = *(const float4*)&Ps[(rq + i) * TPAD + kc0];
                acc[i][0] += pv.x * vv[0].x + pv.y * vv[1].x + pv.z * vv[2].x + pv.w * vv[3].x;
                acc[i][1] += pv.x * vv[0].y + pv.y * vv[1].y + pv.z * vv[2].y + pv.w * vv[3].y;
                acc[i][2] += pv.x * vv[0].z + pv.y * vv[1].z + pv.z * vv[2].z + pv.w * vv[3].z;
                acc[i][3] += pv.x * vv[0].w + pv.y * vv[1].w + pv.z * vv[2].w + pv.w * vv[3].w;
            }
        }
    }

    // epilogue: normalize and write y in [B, NT, C] layout (C = h*Dh + d)
#pragma unroll
    for (int i = 0; i < 4; i++) {
        float l = lrow[rq + i];
        float linv = (l > 0.f) ? 1.f / l : 0.f;
        float* yo = yg + ((size_t)b * NT + (size_t)qt * 64 + rq + i) * Cdim + h * Dh + ck;
        *(float4*)yo = make_float4(acc[i][0] * linv, acc[i][1] * linv,
                                   acc[i][2] * linv, acc[i][3] * linv);
    }
}

// ---------------- launch ----------------------------------------------------
extern "C" void kernel_launch(void* const* d_in, const int* in_sizes, int n_in,
                              void* d_out, int out_size)
{
    const float* x  = (const float*)d_in[0];
    const float* c  = (const float*)d_in[1];
    const void*  mk = d_in[2];
    const float* Wq = (const float*)d_in[3];
    const float* Wk = (const float*)d_in[4];
    const float* Wv = (const float*)d_in[5];
    const float* Wp = (const float*)d_in[6];
    float* out = (float*)d_out;

    float *qp, *kp, *vp, *yp;
    cudaGetSymbolAddress((void**)&qp, g_q);
    cudaGetSymbolAddress((void**)&kp, g_k);
    cudaGetSymbolAddress((void**)&vp, g_v);
    cudaGetSymbolAddress((void**)&yp, g_y);

    cudaFuncSetAttribute(attn_kernel, cudaFuncAttributeMaxDynamicSharedMemorySize,
                         ATT_SMEM_BYTES);

    detect_mask_mode<<<1, 256>>>((const unsigned char*)mk);

    // Q = x @ Wq^T  -> [B,H,NT,Dh]
    gemm_kernel<<<dim3(Cdim / GBN, Bc * NT / GBM), 256>>>(x, nullptr, Wq, qp, NT, 0, 0);
    // K,V = concat(x,c) @ W^T -> [B,H,NKT,Dh]
    gemm_kernel<<<dim3(Cdim / GBN, Bc * NKT / GBM), 256>>>(x, c, Wk, kp, NKT, 1, 0);
    gemm_kernel<<<dim3(Cdim / GBN, Bc * NKT / GBM), 256>>>(x, c, Wv, vp, NKT, 1, 0);

    // attention -> g_y [B,NT,C]
    attn_kernel<<<dim3(NT / 64, Hh, Bc), 256, ATT_SMEM_BYTES>>>(qp, kp, vp, mk, yp);

    // out = y @ Wp^T -> [B,NT,C] (== [B,N,T,C])
    gemm_kernel<<<dim3(Cdim / GBN, Bc * NT / GBM), 256>>>(yp, nullptr, Wp, out, NT, 0, 1);
}